// round 7
// baseline (speedup 1.0000x reference)
#include <cuda_runtime.h>
#include <cstdint>

#define MDIM 8192
#define KDIM 8192
#define NDIM 8192

#define ROW_TILES 148
#define COL_TILES 8
#define NBLK (ROW_TILES * COL_TILES)   // 1184 = 148 SMs * 8 blocks

// ---- scratch (device globals; no allocation allowed) ----
__device__ float g_partial[ROW_TILES * KDIM]; // 4.6 MiB
__device__ float g_wcs[KDIM];                 // 32 KiB
__device__ unsigned g_count = 0;
__device__ volatile unsigned g_sense = 0;

// Sense-reversing grid barrier. All NBLK blocks are co-resident
// (exact-fit grid + __launch_bounds__(256,8)), so spinning is safe.
// State self-resets: count returns to 0, sense flips twice per launch.
__device__ __forceinline__ void grid_barrier() {
    __threadfence();          // make this block's writes globally visible
    __syncthreads();
    if (threadIdx.x == 0) {
        unsigned my = g_sense;
        if (atomicAdd(&g_count, 1u) == NBLK - 1u) {
            g_count = 0;
            __threadfence();
            g_sense = my ^ 1u; // release
        } else {
            while (g_sense == my) { /* spin */ }
        }
    }
    __syncthreads();
    __threadfence();          // acquire side
}

// ============================================================
// One persistent kernel: colsum -> barrier -> reduce -> barrier
// -> rowdot. All phase loops are the previously-measured-best
// variants, unchanged.
// ============================================================
__global__ __launch_bounds__(256, 8) void fused(const float* __restrict__ x,
                                                const float* __restrict__ w,
                                                float* __restrict__ y) {
    const int tid = threadIdx.x;
    const int bid = blockIdx.x;

    // ---- Phase A: partial column sums of W (proven ~41.5us layout) ----
    {
        const int col4 = (bid & (COL_TILES - 1)) * 256 + tid;
        const int rt   = bid >> 3;
        const float4* wp = reinterpret_cast<const float4*>(w) + col4;

        float4 acc = make_float4(0.f, 0.f, 0.f, 0.f);
        #pragma unroll 4
        for (int r = rt; r < NDIM; r += ROW_TILES) {
            float4 v = __ldcs(wp + (size_t)r * (KDIM / 4));
            acc.x += v.x; acc.y += v.y; acc.z += v.z; acc.w += v.w;
        }
        reinterpret_cast<float4*>(g_partial)[(size_t)rt * (KDIM / 4) + col4] = acc;
    }

    grid_barrier();

    // ---- Phase B: fold 148 partials -> g_wcs (blocks 0..31) ----
    if (bid < KDIM / 256) {
        const int k = bid * 256 + tid;
        float s = 0.f;
        #pragma unroll 4
        for (int rt = 0; rt < ROW_TILES; ++rt)
            s += g_partial[(size_t)rt * KDIM + k];
        g_wcs[k] = s;
    }

    grid_barrier();

    // ---- Phase C: y[m] = 0.75 * dot(x[m,:], wcs) (proven R2 loop) ----
    {
        const float4* wp = reinterpret_cast<const float4*>(g_wcs);
        __shared__ float red[8];

        for (int m = bid; m < MDIM; m += NBLK) {
            const float4* xp = reinterpret_cast<const float4*>(x) + (size_t)m * (KDIM / 4);

            float4 acc = make_float4(0.f, 0.f, 0.f, 0.f);
            #pragma unroll 8
            for (int i = tid; i < KDIM / 4; i += 256) {
                float4 a = __ldcs(xp + i);  // one-touch streaming
                float4 b = wp[i];           // hot: L1/L2-resident
                acc.x += a.x * b.x;
                acc.y += a.y * b.y;
                acc.z += a.z * b.z;
                acc.w += a.w * b.w;
            }
            float s = (acc.x + acc.y) + (acc.z + acc.w);

            #pragma unroll
            for (int off = 16; off > 0; off >>= 1)
                s += __shfl_xor_sync(0xFFFFFFFFu, s, off);

            if ((tid & 31) == 0) red[tid >> 5] = s;
            __syncthreads();
            if (tid < 8) {
                float t = red[tid];
                #pragma unroll
                for (int off = 4; off > 0; off >>= 1)
                    t += __shfl_xor_sync(0xFFu, t, off);
                if (tid == 0) y[m] = 0.75f * t;
            }
            __syncthreads();   // protect red[] before next row
        }
    }
}

extern "C" void kernel_launch(void* const* d_in, const int* in_sizes, int n_in,
                              void* d_out, int out_size) {
    const float* x = (const float*)d_in[0];  // [M, K]
    const float* w = (const float*)d_in[1];  // [N, K]
    float* y = (float*)d_out;                // [M, 1]

    fused<<<NBLK, 256>>>(x, w, y);
}

// round 8
// speedup vs baseline: 1.1835x; 1.1835x over previous
#include <cuda_runtime.h>
#include <cstdint>

#define MDIM 8192
#define KDIM 8192
#define NDIM 8192

#define ROW_TILES 148   // one row-tile per SM-resident block slot
#define COL_TILES 8     // 8 * 256 threads * float4 = 8192 columns

// ---- scratch (device globals; no allocation allowed) ----
__device__ float g_partial[ROW_TILES * KDIM]; // 4.6 MiB, overwritten each launch
__device__ float g_wcs[KDIM];                 // 32 KiB column-sum of W

// ============================================================
// Kernel 1: partial column sums of W. (stable ~41.5us, 6.5 TB/s)
// Grid: exactly COL_TILES * ROW_TILES = 1184 blocks = 8 per SM.
// ============================================================
__global__ __launch_bounds__(256, 8) void colsum_partial(const float* __restrict__ w) {
    const int bid  = blockIdx.x;
    const int col4 = (bid & (COL_TILES - 1)) * 256 + threadIdx.x;
    const int rt   = bid >> 3;

    const float4* wp = reinterpret_cast<const float4*>(w) + col4;

    float4 acc = make_float4(0.f, 0.f, 0.f, 0.f);
    #pragma unroll 4
    for (int r = rt; r < NDIM; r += ROW_TILES) {
        float4 v = __ldcs(wp + (size_t)r * (KDIM / 4));
        acc.x += v.x; acc.y += v.y; acc.z += v.z; acc.w += v.w;
    }
    reinterpret_cast<float4*>(g_partial)[(size_t)rt * (KDIM / 4) + col4] = acc;
}

// ============================================================
// Kernel 2: fold the 148 partials -> g_wcs.
// LATENCY-BOUND (32 blocks only): needs maximum MLP. Fully
// unrolled with 4 independent accumulators -> all 148 loads
// issued back-to-back (M_max ~55 outstanding/warp) instead of
// batches of 4. Predicted ~1.5us (was ~12us at unroll 4).
// ============================================================
__global__ __launch_bounds__(256) void colsum_reduce() {
    const int k = blockIdx.x * 256 + threadIdx.x;
    const float* p = g_partial + k;

    float s0 = 0.f, s1 = 0.f, s2 = 0.f, s3 = 0.f;
    #pragma unroll
    for (int rt = 0; rt < ROW_TILES; rt += 4) {
        s0 += p[(size_t)(rt + 0) * KDIM];
        s1 += p[(size_t)(rt + 1) * KDIM];
        s2 += p[(size_t)(rt + 2) * KDIM];
        s3 += p[(size_t)(rt + 3) * KDIM];
    }
    g_wcs[k] = (s0 + s1) + (s2 + s3);
}

// ============================================================
// Kernel 3: y[m] = 0.75 * dot(x[m,:], wcs). Proven R2 loop:
// one 256-thread block per row, stride-256 unroll-8.
// ============================================================
__global__ __launch_bounds__(256, 8) void rowdot(const float* __restrict__ x,
                                                 float* __restrict__ y) {
    const int row = blockIdx.x;
    const int tid = threadIdx.x;
    const float4* xp = reinterpret_cast<const float4*>(x) + (size_t)row * (KDIM / 4);
    const float4* wp = reinterpret_cast<const float4*>(g_wcs);

    float4 acc = make_float4(0.f, 0.f, 0.f, 0.f);
    #pragma unroll 8
    for (int i = tid; i < KDIM / 4; i += 256) {
        float4 a = __ldcs(xp + i);   // one-touch: evict-first
        float4 b = wp[i];            // hot: stays in L2/L1
        acc.x += a.x * b.x;
        acc.y += a.y * b.y;
        acc.z += a.z * b.z;
        acc.w += a.w * b.w;
    }
    float s = (acc.x + acc.y) + (acc.z + acc.w);

    #pragma unroll
    for (int off = 16; off > 0; off >>= 1)
        s += __shfl_xor_sync(0xFFFFFFFFu, s, off);

    __shared__ float red[8];
    if ((tid & 31) == 0) red[tid >> 5] = s;
    __syncthreads();
    if (tid < 8) {
        float t = red[tid];
        #pragma unroll
        for (int off = 4; off > 0; off >>= 1)
            t += __shfl_xor_sync(0xFFu, t, off);
        if (tid == 0) y[row] = 0.75f * t;
    }
}

extern "C" void kernel_launch(void* const* d_in, const int* in_sizes, int n_in,
                              void* d_out, int out_size) {
    const float* x = (const float*)d_in[0];  // [M, K]
    const float* w = (const float*)d_in[1];  // [N, K]
    float* y = (float*)d_out;                // [M, 1]

    colsum_partial<<<COL_TILES * ROW_TILES, 256>>>(w);
    colsum_reduce<<<KDIM / 256, 256>>>();
    rowdot<<<MDIM, 256>>>(x, y);
}